// round 10
// baseline (speedup 1.0000x reference)
#include <cuda_runtime.h>
#include <cstdint>

#define H_IN  1024
#define D     64
#define NB    4
#define LSEQ  2048
#define MROWS (NB*LSEQ)     // 8192
#define LDB   72            // smem row stride (bf16 elems): 144B
#define NTL   16            // KV tiles per attn CTA (half of 32)

// Pre-split projected tensors (hi/lo bf16). Q pre-scaled by 1/(8*ln2).
__device__ uint16_t g_qh[MROWS * D];
__device__ uint16_t g_ql[MROWS * D];
__device__ uint16_t g_kh[MROWS * D];
__device__ uint16_t g_kl[MROWS * D];
__device__ uint16_t g_vh[MROWS * D];
__device__ uint16_t g_vl[MROWS * D];
// Pre-split weights (hi/lo bf16): [3][1024][64]
__device__ uint16_t g_wh[3 * H_IN * D];
__device__ uint16_t g_wl[3 * H_IN * D];
// Split-KV partials (unnormalized O and denominator l)
__device__ float g_p0[MROWS * D];
__device__ float g_p1[MROWS * D];
__device__ float g_l0[MROWS];
__device__ float g_l1[MROWS];

// ---------------------------------------------------------------------------
// helpers
// ---------------------------------------------------------------------------
__device__ __forceinline__ uint32_t s2u(const void* p) {
    uint32_t a;
    asm("{.reg .u64 t; cvta.to.shared.u64 t, %1; cvt.u32.u64 %0, t;}" : "=r"(a) : "l"(p));
    return a;
}
__device__ __forceinline__ void ldsm_x4(uint32_t* r, uint32_t addr) {
    asm volatile("ldmatrix.sync.aligned.m8n8.x4.shared.b16 {%0,%1,%2,%3}, [%4];"
                 : "=r"(r[0]), "=r"(r[1]), "=r"(r[2]), "=r"(r[3]) : "r"(addr));
}
__device__ __forceinline__ void ldsm_x4_t(uint32_t* r, uint32_t addr) {
    asm volatile("ldmatrix.sync.aligned.m8n8.x4.trans.shared.b16 {%0,%1,%2,%3}, [%4];"
                 : "=r"(r[0]), "=r"(r[1]), "=r"(r[2]), "=r"(r[3]) : "r"(addr));
}
__device__ __forceinline__ void mma16816(float* c, const uint32_t* a, const uint32_t* b) {
    asm volatile("mma.sync.aligned.m16n8k16.row.col.f32.bf16.bf16.f32 "
                 "{%0,%1,%2,%3}, {%4,%5,%6,%7}, {%8,%9}, {%0,%1,%2,%3};"
                 : "+f"(c[0]), "+f"(c[1]), "+f"(c[2]), "+f"(c[3])
                 : "r"(a[0]), "r"(a[1]), "r"(a[2]), "r"(a[3]), "r"(b[0]), "r"(b[1]));
}
__device__ __forceinline__ void split4(float4 v, uint2& hi, uint2& lo) {
    uint32_t ux = __float_as_uint(v.x), uy = __float_as_uint(v.y);
    uint32_t uz = __float_as_uint(v.z), uw = __float_as_uint(v.w);
    asm("prmt.b32 %0, %1, %2, 0x7632;" : "=r"(hi.x) : "r"(ux), "r"(uy));
    asm("prmt.b32 %0, %1, %2, 0x7632;" : "=r"(hi.y) : "r"(uz), "r"(uw));
    float rx = v.x - __uint_as_float(ux & 0xFFFF0000u);
    float ry = v.y - __uint_as_float(uy & 0xFFFF0000u);
    float rz = v.z - __uint_as_float(uz & 0xFFFF0000u);
    float rw = v.w - __uint_as_float(uw & 0xFFFF0000u);
    asm("cvt.rn.bf16x2.f32 %0, %1, %2;" : "=r"(lo.x) : "f"(ry), "f"(rx));
    asm("cvt.rn.bf16x2.f32 %0, %1, %2;" : "=r"(lo.y) : "f"(rw), "f"(rz));
}
__device__ __forceinline__ uint32_t pack_hi(float a, float b) {
    uint32_t r;
    asm("prmt.b32 %0, %1, %2, 0x7632;" : "=r"(r)
        : "r"(__float_as_uint(a)), "r"(__float_as_uint(b)));
    return r;
}
__device__ __forceinline__ uint32_t pack_lo(float a, float b) {
    float ra = a - __uint_as_float(__float_as_uint(a) & 0xFFFF0000u);
    float rb = b - __uint_as_float(__float_as_uint(b) & 0xFFFF0000u);
    uint32_t r;
    asm("cvt.rn.bf16x2.f32 %0, %1, %2;" : "=r"(r) : "f"(rb), "f"(ra));
    return r;
}
__device__ __forceinline__ float ex2(float x) {
    float y;
    asm("ex2.approx.f32 %0, %1;" : "=f"(y) : "f"(x));
    return y;
}
template <int N> __device__ __forceinline__ void cp_wait() {
    asm volatile("cp.async.wait_group %0;" :: "n"(N) : "memory");
}
__device__ __forceinline__ void cp_commit() {
    asm volatile("cp.async.commit_group;" ::: "memory");
}
__device__ __forceinline__ void cp16(uint32_t saddr, const void* gaddr) {
    asm volatile("cp.async.cg.shared.global [%0], [%1], 16;"
                 :: "r"(saddr), "l"(gaddr) : "memory");
}

// ---------------------------------------------------------------------------
// Kernel 0: split weights once. grid (64, 3), 256 threads.
// ---------------------------------------------------------------------------
__global__ __launch_bounds__(256) void presplit_w(
    const float* __restrict__ Wq, const float* __restrict__ Wk, const float* __restrict__ Wv)
{
    const float* W = (blockIdx.y == 0) ? Wq : (blockIdx.y == 1) ? Wk : Wv;
    const int i = (blockIdx.x * 256 + threadIdx.x) * 4;
    float4 v = *(const float4*)&W[i];
    uint2 hi, lo; split4(v, hi, lo);
    const size_t o = (size_t)blockIdx.y * H_IN * D + i;
    *(uint2*)&g_wh[o] = hi;
    *(uint2*)&g_wl[o] = lo;
}

// ---------------------------------------------------------------------------
// Kernel 1: QKV projection — ROUND-8 STRUCTURE, W from pre-split globals.
// 128 threads (4 warps), CTA tile M=64, K-chunk 64; grid (128, 3).
// ---------------------------------------------------------------------------
__global__ __launch_bounds__(128) void proj_mma(
    const float* __restrict__ Xq, const float* __restrict__ Xk, const float* __restrict__ Xv,
    const float* __restrict__ Bq, const float* __restrict__ Bk, const float* __restrict__ Bv)
{
    const int wsel = blockIdx.y;
    const float* X; const float* Bias;
    uint16_t* outH; uint16_t* outL; float scale;
    switch (wsel) {
        case 0:  X = Xq; Bias = Bq; outH = g_qh; outL = g_ql;
                 scale = 0.18033688f; break;             // 1/(8*ln2)
        case 1:  X = Xk; Bias = Bk; outH = g_kh; outL = g_kl; scale = 1.0f; break;
        default: X = Xv; Bias = Bv; outH = g_vh; outL = g_vl; scale = 1.0f; break;
    }

    extern __shared__ uint16_t sp[];
    uint16_t* Ah = sp;
    uint16_t* Al = Ah + 64 * LDB;
    uint16_t* Bh = Al + 64 * LDB;
    uint16_t* Bl = Bh + 64 * LDB;

    const int tid  = threadIdx.x;
    const int lane = tid & 31;
    const int w    = tid >> 5;
    const int m0   = blockIdx.x * 64;
    const int g    = lane >> 3, l8 = lane & 7;

    float acc[8][4];
    #pragma unroll
    for (int nt = 0; nt < 8; nt++)
        #pragma unroll
        for (int j = 0; j < 4; j++) acc[nt][j] = 0.f;

    // prefetch X chunk 0
    float4 xv[8];
    #pragma unroll
    for (int i = 0; i < 8; i++) {
        const int idx = tid + i * 128;
        xv[i] = *(const float4*)&X[(size_t)(m0 + (idx >> 4)) * H_IN + (idx & 15) * 4];
    }

    const uint16_t* WH = g_wh + (size_t)wsel * H_IN * D;
    const uint16_t* WL = g_wl + (size_t)wsel * H_IN * D;

    for (int kk = 0; kk < H_IN; kk += 64) {
        // load W chunk from pre-split globals (already bf16 hi/lo)
        uint4 wh[4], wl[4];
        #pragma unroll
        for (int i = 0; i < 4; i++) {
            const int idx = tid + i * 128;                 // 0..511
            const int row = idx >> 3, c8 = (idx & 7) * 8;  // 8 uint4 per 64-elem row
            wh[i] = *(const uint4*)&WH[(size_t)(kk + row) * D + c8];
            wl[i] = *(const uint4*)&WL[(size_t)(kk + row) * D + c8];
        }
        // store X chunk (split in regs)
        #pragma unroll
        for (int i = 0; i < 8; i++) {
            const int idx = tid + i * 128;
            const int row = idx >> 4, f4 = idx & 15;
            uint2 hi, lo; split4(xv[i], hi, lo);
            *(uint2*)&Ah[row * LDB + f4 * 4] = hi;
            *(uint2*)&Al[row * LDB + f4 * 4] = lo;
        }
        // store W chunk (straight copy)
        #pragma unroll
        for (int i = 0; i < 4; i++) {
            const int idx = tid + i * 128;
            const int row = idx >> 3, c8 = (idx & 7) * 8;
            *(uint4*)&Bh[row * LDB + c8] = wh[i];
            *(uint4*)&Bl[row * LDB + c8] = wl[i];
        }
        __syncthreads();

        // prefetch next X chunk (hidden under mma)
        if (kk + 64 < H_IN) {
            #pragma unroll
            for (int i = 0; i < 8; i++) {
                const int idx = tid + i * 128;
                xv[i] = *(const float4*)&X[(size_t)(m0 + (idx >> 4)) * H_IN + kk + 64 + (idx & 15) * 4];
            }
        }

        uint32_t ah[4], al[4], bb[4], bl[4];
        #pragma unroll
        for (int kt = 0; kt < 4; kt++) {
            const int aoff = (w * 16 + (lane & 15)) * LDB + kt * 16 + (lane >> 4) * 8;
            ldsm_x4(ah, s2u(&Ah[aoff]));
            ldsm_x4(al, s2u(&Al[aoff]));
            #pragma unroll
            for (int p = 0; p < 4; p++) {
                const int row = kt * 16 + (g & 1) * 8 + l8;
                const int col = (2 * p + (g >> 1)) * 8;
                ldsm_x4_t(bb, s2u(&Bh[row * LDB + col]));
                ldsm_x4_t(bl, s2u(&Bl[row * LDB + col]));
                mma16816(acc[2*p],   ah, bb);     mma16816(acc[2*p],   ah, bl);
                mma16816(acc[2*p],   al, bb);
                mma16816(acc[2*p+1], ah, bb + 2); mma16816(acc[2*p+1], ah, bl + 2);
                mma16816(acc[2*p+1], al, bb + 2);
            }
        }
        __syncthreads();
    }

    const int r0 = m0 + w * 16 + (lane >> 2);
    #pragma unroll
    for (int nt = 0; nt < 8; nt++) {
        const int c = nt * 8 + (lane & 3) * 2;
        const float2 b2 = *(const float2*)&Bias[c];
        const float y0 = (acc[nt][0] + b2.x) * scale;
        const float y1 = (acc[nt][1] + b2.y) * scale;
        const float y2 = (acc[nt][2] + b2.x) * scale;
        const float y3 = (acc[nt][3] + b2.y) * scale;
        *(uint32_t*)&outH[(size_t)r0 * D + c]       = pack_hi(y0, y1);
        *(uint32_t*)&outL[(size_t)r0 * D + c]       = pack_lo(y0, y1);
        *(uint32_t*)&outH[(size_t)(r0 + 8) * D + c] = pack_hi(y2, y3);
        *(uint32_t*)&outL[(size_t)(r0 + 8) * D + c] = pack_lo(y2, y3);
    }
}

// ---------------------------------------------------------------------------
// Kernel 2: flash attention (unchanged, round-8 measured version).
// split-KV(2), no-max base-2 softmax, warp-independent rows.
// ---------------------------------------------------------------------------
#define STG 36864
#define ARR 9216

__device__ __forceinline__ void issue_kv(uint32_t kvb, int n, int tile, int tid) {
    #pragma unroll
    for (int j = 0; j < 16; j++) {
        const int cc = tid + j * 128;
        const int arr = cc >> 9, rem = cc & 511, row = rem >> 3, col = rem & 7;
        const uint16_t* gp = (arr == 0) ? g_kh : (arr == 1) ? g_kl
                            : (arr == 2) ? g_vh : g_vl;
        cp16(kvb + arr * ARR + row * 144 + col * 16,
             gp + ((size_t)(n * LSEQ + tile * 64 + row)) * D + col * 8);
    }
    cp_commit();
}

__global__ __launch_bounds__(128) void attn_mma(void)
{
    extern __shared__ uint16_t sa[];
    uint16_t* Qh = sa;
    uint16_t* Ql = Qh + 64 * LDB;
    uint16_t* KV = Ql + 64 * LDB;
    const uint32_t kvb = s2u(KV);

    const int tid  = threadIdx.x;
    const int lane = tid & 31;
    const int w    = tid >> 5;
    const int g    = lane >> 3, l8 = lane & 7;
    const int n    = blockIdx.y;
    const int q0   = blockIdx.x * 64;
    const int z    = blockIdx.z;
    const int off  = (blockIdx.x * 7 + blockIdx.y * 5 + z * 3) & (NTL - 1);
    #define TL(t) (z * NTL + (((t) + off) & (NTL - 1)))

    float* gP = z ? g_p1 : g_p0;
    float* gL = z ? g_l1 : g_l0;

    issue_kv(kvb + 0 * STG, n, TL(0), tid);
    #pragma unroll
    for (int j = 0; j < 8; j++) {
        const int cc = tid + j * 128;
        const int a = cc >> 9, rem = cc & 511, row = rem >> 3, col = rem & 7;
        uint16_t* spq = a ? Ql : Qh;
        *(uint4*)&spq[row * LDB + col * 8] =
            *(const uint4*)&(a ? g_ql : g_qh)[((size_t)(n * LSEQ + q0 + row)) * D + col * 8];
    }
    __syncthreads();

    uint32_t qh[4][4], ql[4][4];
    #pragma unroll
    for (int kt = 0; kt < 4; kt++) {
        const int aoff = (w * 16 + (lane & 15)) * LDB + kt * 16 + (lane >> 4) * 8;
        ldsm_x4(qh[kt], s2u(&Qh[aoff]));
        ldsm_x4(ql[kt], s2u(&Ql[aoff]));
    }

    float o[8][4];
    #pragma unroll
    for (int nt = 0; nt < 8; nt++)
        #pragma unroll
        for (int j = 0; j < 4; j++) o[nt][j] = 0.f;
    float l0 = 0.f, l1 = 0.f;

    for (int t = 0; t < NTL; t++) {
        const uint32_t st = kvb + (t & 1) * STG;
        if (t + 1 < NTL) { issue_kv(kvb + ((t + 1) & 1) * STG, n, TL(t + 1), tid); cp_wait<1>(); }
        else             { cp_wait<0>(); }
        __syncthreads();

        float s[8][4];
        #pragma unroll
        for (int nt = 0; nt < 8; nt++)
            #pragma unroll
            for (int j = 0; j < 4; j++) s[nt][j] = 0.f;

        #pragma unroll
        for (int kt = 0; kt < 4; kt++) {
            #pragma unroll
            for (int p = 0; p < 4; p++) {
                const int row  = p * 16 + (g >> 1) * 8 + l8;
                const int koff = kt * 16 + (g & 1) * 8;
                uint32_t kb[4], kl_[4];
                ldsm_x4(kb,  st + 0 * ARR + (row * LDB + koff) * 2);
                ldsm_x4(kl_, st + 1 * ARR + (row * LDB + koff) * 2);
                mma16816(s[2*p],   qh[kt], kb);     mma16816(s[2*p],   qh[kt], kl_);
                mma16816(s[2*p],   ql[kt], kb);
                mma16816(s[2*p+1], qh[kt], kb + 2); mma16816(s[2*p+1], qh[kt], kl_ + 2);
                mma16816(s[2*p+1], ql[kt], kb + 2);
            }
        }

        float rs0 = 0.f, rs1 = 0.f;
        #pragma unroll
        for (int nt = 0; nt < 8; nt++) {
            s[nt][0] = ex2(s[nt][0]); rs0 += s[nt][0];
            s[nt][1] = ex2(s[nt][1]); rs0 += s[nt][1];
            s[nt][2] = ex2(s[nt][2]); rs1 += s[nt][2];
            s[nt][3] = ex2(s[nt][3]); rs1 += s[nt][3];
        }
        rs0 += __shfl_xor_sync(0xffffffffu, rs0, 1);
        rs0 += __shfl_xor_sync(0xffffffffu, rs0, 2);
        rs1 += __shfl_xor_sync(0xffffffffu, rs1, 1);
        rs1 += __shfl_xor_sync(0xffffffffu, rs1, 2);
        l0 += rs0;
        l1 += rs1;

        #pragma unroll
        for (int kt = 0; kt < 4; kt++) {
            uint32_t ph[4], pl[4];
            ph[0] = pack_hi(s[2*kt][0],   s[2*kt][1]);
            ph[1] = pack_hi(s[2*kt][2],   s[2*kt][3]);
            ph[2] = pack_hi(s[2*kt+1][0], s[2*kt+1][1]);
            ph[3] = pack_hi(s[2*kt+1][2], s[2*kt+1][3]);
            pl[0] = pack_lo(s[2*kt][0],   s[2*kt][1]);
            pl[1] = pack_lo(s[2*kt][2],   s[2*kt][3]);
            pl[2] = pack_lo(s[2*kt+1][0], s[2*kt+1][1]);
            pl[3] = pack_lo(s[2*kt+1][2], s[2*kt+1][3]);
            #pragma unroll
            for (int p = 0; p < 4; p++) {
                const int row = kt * 16 + (g & 1) * 8 + l8;
                const int col = (2 * p + (g >> 1)) * 8;
                uint32_t vb[4], vl_[4];
                ldsm_x4_t(vb,  st + 2 * ARR + (row * LDB + col) * 2);
                ldsm_x4_t(vl_, st + 3 * ARR + (row * LDB + col) * 2);
                mma16816(o[2*p],   ph, vb);     mma16816(o[2*p],   ph, vl_);
                mma16816(o[2*p],   pl, vb);
                mma16816(o[2*p+1], ph, vb + 2); mma16816(o[2*p+1], ph, vl_ + 2);
                mma16816(o[2*p+1], pl, vb + 2);
            }
        }
        __syncthreads();
    }

    const int r = q0 + w * 16 + (lane >> 2);
    #pragma unroll
    for (int nt = 0; nt < 8; nt++) {
        const int c = nt * 8 + (lane & 3) * 2;
        *(float2*)&gP[((size_t)(n * LSEQ + r)) * D + c]     = make_float2(o[nt][0], o[nt][1]);
        *(float2*)&gP[((size_t)(n * LSEQ + r + 8)) * D + c] = make_float2(o[nt][2], o[nt][3]);
    }
    if ((lane & 3) == 0) {
        gL[n * LSEQ + r]     = l0;
        gL[n * LSEQ + r + 8] = l1;
    }
}

// ---------------------------------------------------------------------------
// Kernel 3: combine halves: out = (P0+P1)/(l0+l1). 2 float4/thread (same row).
// ---------------------------------------------------------------------------
__global__ __launch_bounds__(256) void combine_k(float* __restrict__ out)
{
    const int id = blockIdx.x * 256 + threadIdx.x;   // 256 blocks x 256 = 65536
    const int e0 = id * 8;                            // 8 elems, one row
    const int row = e0 >> 6, c = e0 & 63;
    const float inv = 1.f / (g_l0[row] + g_l1[row]);
    const float4 a0 = *(const float4*)&g_p0[(size_t)row * D + c];
    const float4 a1 = *(const float4*)&g_p0[(size_t)row * D + c + 4];
    const float4 b0 = *(const float4*)&g_p1[(size_t)row * D + c];
    const float4 b1 = *(const float4*)&g_p1[(size_t)row * D + c + 4];
    float4 r0, r1;
    r0.x = (a0.x + b0.x) * inv; r0.y = (a0.y + b0.y) * inv;
    r0.z = (a0.z + b0.z) * inv; r0.w = (a0.w + b0.w) * inv;
    r1.x = (a1.x + b1.x) * inv; r1.y = (a1.y + b1.y) * inv;
    r1.z = (a1.z + b1.z) * inv; r1.w = (a1.w + b1.w) * inv;
    *(float4*)&out[(size_t)row * D + c]     = r0;
    *(float4*)&out[(size_t)row * D + c + 4] = r1;
}

// ---------------------------------------------------------------------------
// Launch
// ---------------------------------------------------------------------------
extern "C" void kernel_launch(void* const* d_in, const int* in_sizes, int n_in,
                              void* d_out, int out_size)
{
    const float* q  = (const float*)d_in[0];
    const float* k  = (const float*)d_in[1];
    const float* v  = (const float*)d_in[2];
    const float* Wq = (const float*)d_in[3];
    const float* bq = (const float*)d_in[4];
    const float* Wk = (const float*)d_in[5];
    const float* bk = (const float*)d_in[6];
    const float* Wv = (const float*)d_in[7];
    const float* bv = (const float*)d_in[8];
    float* out = (float*)d_out;

    const int smem_proj = 4 * 64 * LDB * 2;                 // 36864 B
    const int smem_attn = 2 * 64 * LDB * 2 + 2 * STG;       // 92160 B
    cudaFuncSetAttribute(proj_mma, cudaFuncAttributeMaxDynamicSharedMemorySize, smem_proj);
    cudaFuncSetAttribute(attn_mma, cudaFuncAttributeMaxDynamicSharedMemorySize, smem_attn);

    presplit_w<<<dim3(64, 3), 256>>>(Wq, Wk, Wv);
    proj_mma<<<dim3(MROWS / 64, 3), 128, smem_proj>>>(q, k, v, bq, bk, bv);
    attn_mma<<<dim3(LSEQ / 64, NB, 2), 128, smem_attn>>>();
    combine_k<<<256, 256>>>(out);
}

// round 11
// speedup vs baseline: 1.1799x; 1.1799x over previous
#include <cuda_runtime.h>
#include <cstdint>

#define H_IN  1024
#define D     64
#define NB    4
#define LSEQ  2048
#define MROWS (NB*LSEQ)     // 8192
#define LDB   72            // smem row stride (bf16 elems): 144B
#define NTL   16            // KV tiles per attn CTA (half of 32)

// Pre-split projected tensors (hi/lo bf16). Q pre-scaled by 1/(8*ln2).
__device__ uint16_t g_qh[MROWS * D];
__device__ uint16_t g_ql[MROWS * D];
__device__ uint16_t g_kh[MROWS * D];
__device__ uint16_t g_kl[MROWS * D];
__device__ uint16_t g_vh[MROWS * D];
__device__ uint16_t g_vl[MROWS * D];
// Split-KV partials (unnormalized O and denominator l)
__device__ float g_p0[MROWS * D];
__device__ float g_p1[MROWS * D];
__device__ float g_l0[MROWS];
__device__ float g_l1[MROWS];

// ---------------------------------------------------------------------------
// helpers
// ---------------------------------------------------------------------------
__device__ __forceinline__ uint32_t s2u(const void* p) {
    uint32_t a;
    asm("{.reg .u64 t; cvta.to.shared.u64 t, %1; cvt.u32.u64 %0, t;}" : "=r"(a) : "l"(p));
    return a;
}
__device__ __forceinline__ void ldsm_x4(uint32_t* r, uint32_t addr) {
    asm volatile("ldmatrix.sync.aligned.m8n8.x4.shared.b16 {%0,%1,%2,%3}, [%4];"
                 : "=r"(r[0]), "=r"(r[1]), "=r"(r[2]), "=r"(r[3]) : "r"(addr));
}
__device__ __forceinline__ void ldsm_x4_t(uint32_t* r, uint32_t addr) {
    asm volatile("ldmatrix.sync.aligned.m8n8.x4.trans.shared.b16 {%0,%1,%2,%3}, [%4];"
                 : "=r"(r[0]), "=r"(r[1]), "=r"(r[2]), "=r"(r[3]) : "r"(addr));
}
__device__ __forceinline__ void mma16816(float* c, const uint32_t* a, const uint32_t* b) {
    asm volatile("mma.sync.aligned.m16n8k16.row.col.f32.bf16.bf16.f32 "
                 "{%0,%1,%2,%3}, {%4,%5,%6,%7}, {%8,%9}, {%0,%1,%2,%3};"
                 : "+f"(c[0]), "+f"(c[1]), "+f"(c[2]), "+f"(c[3])
                 : "r"(a[0]), "r"(a[1]), "r"(a[2]), "r"(a[3]), "r"(b[0]), "r"(b[1]));
}
__device__ __forceinline__ void split4(float4 v, uint2& hi, uint2& lo) {
    uint32_t ux = __float_as_uint(v.x), uy = __float_as_uint(v.y);
    uint32_t uz = __float_as_uint(v.z), uw = __float_as_uint(v.w);
    asm("prmt.b32 %0, %1, %2, 0x7632;" : "=r"(hi.x) : "r"(ux), "r"(uy));
    asm("prmt.b32 %0, %1, %2, 0x7632;" : "=r"(hi.y) : "r"(uz), "r"(uw));
    float rx = v.x - __uint_as_float(ux & 0xFFFF0000u);
    float ry = v.y - __uint_as_float(uy & 0xFFFF0000u);
    float rz = v.z - __uint_as_float(uz & 0xFFFF0000u);
    float rw = v.w - __uint_as_float(uw & 0xFFFF0000u);
    asm("cvt.rn.bf16x2.f32 %0, %1, %2;" : "=r"(lo.x) : "f"(ry), "f"(rx));
    asm("cvt.rn.bf16x2.f32 %0, %1, %2;" : "=r"(lo.y) : "f"(rw), "f"(rz));
}
__device__ __forceinline__ uint32_t pack_hi(float a, float b) {
    uint32_t r;
    asm("prmt.b32 %0, %1, %2, 0x7632;" : "=r"(r)
        : "r"(__float_as_uint(a)), "r"(__float_as_uint(b)));
    return r;
}
__device__ __forceinline__ uint32_t pack_lo(float a, float b) {
    float ra = a - __uint_as_float(__float_as_uint(a) & 0xFFFF0000u);
    float rb = b - __uint_as_float(__float_as_uint(b) & 0xFFFF0000u);
    uint32_t r;
    asm("cvt.rn.bf16x2.f32 %0, %1, %2;" : "=r"(r) : "f"(rb), "f"(ra));
    return r;
}
__device__ __forceinline__ float ex2(float x) {
    float y;
    asm("ex2.approx.f32 %0, %1;" : "=f"(y) : "f"(x));
    return y;
}
template <int N> __device__ __forceinline__ void cp_wait() {
    asm volatile("cp.async.wait_group %0;" :: "n"(N) : "memory");
}
__device__ __forceinline__ void cp_commit() {
    asm volatile("cp.async.commit_group;" ::: "memory");
}
__device__ __forceinline__ void cp16(uint32_t saddr, const void* gaddr) {
    asm volatile("cp.async.cg.shared.global [%0], [%1], 16;"
                 :: "r"(saddr), "l"(gaddr) : "memory");
}

// ---------------------------------------------------------------------------
// Kernel 1: QKV projection — EXACT round-8 version (in-kernel W split).
// 128 threads (4 warps), CTA tile M=64, K-chunk 64; grid (128, 3).
// ---------------------------------------------------------------------------
__global__ __launch_bounds__(128) void proj_mma(
    const float* __restrict__ Xq, const float* __restrict__ Xk, const float* __restrict__ Xv,
    const float* __restrict__ Wq, const float* __restrict__ Wk, const float* __restrict__ Wv,
    const float* __restrict__ Bq, const float* __restrict__ Bk, const float* __restrict__ Bv)
{
    const float* X; const float* W; const float* Bias;
    uint16_t* outH; uint16_t* outL; float scale;
    switch (blockIdx.y) {
        case 0:  X = Xq; W = Wq; Bias = Bq; outH = g_qh; outL = g_ql;
                 scale = 0.18033688f; break;             // 1/(8*ln2)
        case 1:  X = Xk; W = Wk; Bias = Bk; outH = g_kh; outL = g_kl; scale = 1.0f; break;
        default: X = Xv; W = Wv; Bias = Bv; outH = g_vh; outL = g_vl; scale = 1.0f; break;
    }

    extern __shared__ uint16_t sp[];
    uint16_t* Ah = sp;
    uint16_t* Al = Ah + 64 * LDB;
    uint16_t* Bh = Al + 64 * LDB;
    uint16_t* Bl = Bh + 64 * LDB;

    const int tid  = threadIdx.x;
    const int lane = tid & 31;
    const int w    = tid >> 5;
    const int m0   = blockIdx.x * 64;
    const int g    = lane >> 3, l8 = lane & 7;

    float acc[8][4];
    #pragma unroll
    for (int nt = 0; nt < 8; nt++)
        #pragma unroll
        for (int j = 0; j < 4; j++) acc[nt][j] = 0.f;

    float4 xv[8];
    #pragma unroll
    for (int i = 0; i < 8; i++) {
        const int idx = tid + i * 128;
        xv[i] = *(const float4*)&X[(size_t)(m0 + (idx >> 4)) * H_IN + (idx & 15) * 4];
    }

    for (int kk = 0; kk < H_IN; kk += 64) {
        float4 wv[8];
        #pragma unroll
        for (int i = 0; i < 8; i++) {
            const int idx = tid + i * 128;
            wv[i] = *(const float4*)&W[(size_t)(kk + (idx >> 4)) * D + (idx & 15) * 4];
        }
        #pragma unroll
        for (int i = 0; i < 8; i++) {
            const int idx = tid + i * 128;
            const int row = idx >> 4, f4 = idx & 15;
            uint2 hi, lo; split4(xv[i], hi, lo);
            *(uint2*)&Ah[row * LDB + f4 * 4] = hi;
            *(uint2*)&Al[row * LDB + f4 * 4] = lo;
        }
        #pragma unroll
        for (int i = 0; i < 8; i++) {
            const int idx = tid + i * 128;
            const int row = idx >> 4, f4 = idx & 15;
            uint2 hi, lo; split4(wv[i], hi, lo);
            *(uint2*)&Bh[row * LDB + f4 * 4] = hi;
            *(uint2*)&Bl[row * LDB + f4 * 4] = lo;
        }
        __syncthreads();

        if (kk + 64 < H_IN) {
            #pragma unroll
            for (int i = 0; i < 8; i++) {
                const int idx = tid + i * 128;
                xv[i] = *(const float4*)&X[(size_t)(m0 + (idx >> 4)) * H_IN + kk + 64 + (idx & 15) * 4];
            }
        }

        uint32_t ah[4], al[4], bb[4], bl[4];
        #pragma unroll
        for (int kt = 0; kt < 4; kt++) {
            const int aoff = (w * 16 + (lane & 15)) * LDB + kt * 16 + (lane >> 4) * 8;
            ldsm_x4(ah, s2u(&Ah[aoff]));
            ldsm_x4(al, s2u(&Al[aoff]));
            #pragma unroll
            for (int p = 0; p < 4; p++) {
                const int row = kt * 16 + (g & 1) * 8 + l8;
                const int col = (2 * p + (g >> 1)) * 8;
                ldsm_x4_t(bb, s2u(&Bh[row * LDB + col]));
                ldsm_x4_t(bl, s2u(&Bl[row * LDB + col]));
                mma16816(acc[2*p],   ah, bb);     mma16816(acc[2*p],   ah, bl);
                mma16816(acc[2*p],   al, bb);
                mma16816(acc[2*p+1], ah, bb + 2); mma16816(acc[2*p+1], ah, bl + 2);
                mma16816(acc[2*p+1], al, bb + 2);
            }
        }
        __syncthreads();
    }

    const int r0 = m0 + w * 16 + (lane >> 2);
    #pragma unroll
    for (int nt = 0; nt < 8; nt++) {
        const int c = nt * 8 + (lane & 3) * 2;
        const float2 b2 = *(const float2*)&Bias[c];
        const float y0 = (acc[nt][0] + b2.x) * scale;
        const float y1 = (acc[nt][1] + b2.y) * scale;
        const float y2 = (acc[nt][2] + b2.x) * scale;
        const float y3 = (acc[nt][3] + b2.y) * scale;
        *(uint32_t*)&outH[(size_t)r0 * D + c]       = pack_hi(y0, y1);
        *(uint32_t*)&outL[(size_t)r0 * D + c]       = pack_lo(y0, y1);
        *(uint32_t*)&outH[(size_t)(r0 + 8) * D + c] = pack_hi(y2, y3);
        *(uint32_t*)&outL[(size_t)(r0 + 8) * D + c] = pack_lo(y2, y3);
    }
}

// ---------------------------------------------------------------------------
// Kernel 2: flash attention (round-8 version; only change: the per-tile
// cross-thread l-reduction is deferred to ONE shuffle pass after the loop).
// split-KV(2), no-max base-2 softmax, warp-independent rows.
// ---------------------------------------------------------------------------
#define STG 36864
#define ARR 9216

__device__ __forceinline__ void issue_kv(uint32_t kvb, int n, int tile, int tid) {
    #pragma unroll
    for (int j = 0; j < 16; j++) {
        const int cc = tid + j * 128;
        const int arr = cc >> 9, rem = cc & 511, row = rem >> 3, col = rem & 7;
        const uint16_t* gp = (arr == 0) ? g_kh : (arr == 1) ? g_kl
                            : (arr == 2) ? g_vh : g_vl;
        cp16(kvb + arr * ARR + row * 144 + col * 16,
             gp + ((size_t)(n * LSEQ + tile * 64 + row)) * D + col * 8);
    }
    cp_commit();
}

__global__ __launch_bounds__(128) void attn_mma(void)
{
    extern __shared__ uint16_t sa[];
    uint16_t* Qh = sa;
    uint16_t* Ql = Qh + 64 * LDB;
    uint16_t* KV = Ql + 64 * LDB;
    const uint32_t kvb = s2u(KV);

    const int tid  = threadIdx.x;
    const int lane = tid & 31;
    const int w    = tid >> 5;
    const int g    = lane >> 3, l8 = lane & 7;
    const int n    = blockIdx.y;
    const int q0   = blockIdx.x * 64;
    const int z    = blockIdx.z;
    const int off  = (blockIdx.x * 7 + blockIdx.y * 5 + z * 3) & (NTL - 1);
    #define TL(t) (z * NTL + (((t) + off) & (NTL - 1)))

    float* gP = z ? g_p1 : g_p0;
    float* gL = z ? g_l1 : g_l0;

    issue_kv(kvb + 0 * STG, n, TL(0), tid);
    #pragma unroll
    for (int j = 0; j < 8; j++) {
        const int cc = tid + j * 128;
        const int a = cc >> 9, rem = cc & 511, row = rem >> 3, col = rem & 7;
        uint16_t* spq = a ? Ql : Qh;
        *(uint4*)&spq[row * LDB + col * 8] =
            *(const uint4*)&(a ? g_ql : g_qh)[((size_t)(n * LSEQ + q0 + row)) * D + col * 8];
    }
    __syncthreads();

    uint32_t qh[4][4], ql[4][4];
    #pragma unroll
    for (int kt = 0; kt < 4; kt++) {
        const int aoff = (w * 16 + (lane & 15)) * LDB + kt * 16 + (lane >> 4) * 8;
        ldsm_x4(qh[kt], s2u(&Qh[aoff]));
        ldsm_x4(ql[kt], s2u(&Ql[aoff]));
    }

    float o[8][4];
    #pragma unroll
    for (int nt = 0; nt < 8; nt++)
        #pragma unroll
        for (int j = 0; j < 4; j++) o[nt][j] = 0.f;
    float l0 = 0.f, l1 = 0.f;    // per-thread partials; reduced once at end

    for (int t = 0; t < NTL; t++) {
        const uint32_t st = kvb + (t & 1) * STG;
        if (t + 1 < NTL) { issue_kv(kvb + ((t + 1) & 1) * STG, n, TL(t + 1), tid); cp_wait<1>(); }
        else             { cp_wait<0>(); }
        __syncthreads();

        float s[8][4];
        #pragma unroll
        for (int nt = 0; nt < 8; nt++)
            #pragma unroll
            for (int j = 0; j < 4; j++) s[nt][j] = 0.f;

        #pragma unroll
        for (int kt = 0; kt < 4; kt++) {
            #pragma unroll
            for (int p = 0; p < 4; p++) {
                const int row  = p * 16 + (g >> 1) * 8 + l8;
                const int koff = kt * 16 + (g & 1) * 8;
                uint32_t kb[4], kl_[4];
                ldsm_x4(kb,  st + 0 * ARR + (row * LDB + koff) * 2);
                ldsm_x4(kl_, st + 1 * ARR + (row * LDB + koff) * 2);
                mma16816(s[2*p],   qh[kt], kb);     mma16816(s[2*p],   qh[kt], kl_);
                mma16816(s[2*p],   ql[kt], kb);
                mma16816(s[2*p+1], qh[kt], kb + 2); mma16816(s[2*p+1], qh[kt], kl_ + 2);
                mma16816(s[2*p+1], ql[kt], kb + 2);
            }
        }

        // no-max base-2 softmax; l kept as per-thread partial (no shuffles here)
        #pragma unroll
        for (int nt = 0; nt < 8; nt++) {
            s[nt][0] = ex2(s[nt][0]); l0 += s[nt][0];
            s[nt][1] = ex2(s[nt][1]); l0 += s[nt][1];
            s[nt][2] = ex2(s[nt][2]); l1 += s[nt][2];
            s[nt][3] = ex2(s[nt][3]); l1 += s[nt][3];
        }

        #pragma unroll
        for (int kt = 0; kt < 4; kt++) {
            uint32_t ph[4], pl[4];
            ph[0] = pack_hi(s[2*kt][0],   s[2*kt][1]);
            ph[1] = pack_hi(s[2*kt][2],   s[2*kt][3]);
            ph[2] = pack_hi(s[2*kt+1][0], s[2*kt+1][1]);
            ph[3] = pack_hi(s[2*kt+1][2], s[2*kt+1][3]);
            pl[0] = pack_lo(s[2*kt][0],   s[2*kt][1]);
            pl[1] = pack_lo(s[2*kt][2],   s[2*kt][3]);
            pl[2] = pack_lo(s[2*kt+1][0], s[2*kt+1][1]);
            pl[3] = pack_lo(s[2*kt+1][2], s[2*kt+1][3]);
            #pragma unroll
            for (int p = 0; p < 4; p++) {
                const int row = kt * 16 + (g & 1) * 8 + l8;
                const int col = (2 * p + (g >> 1)) * 8;
                uint32_t vb[4], vl_[4];
                ldsm_x4_t(vb,  st + 2 * ARR + (row * LDB + col) * 2);
                ldsm_x4_t(vl_, st + 3 * ARR + (row * LDB + col) * 2);
                mma16816(o[2*p],   ph, vb);     mma16816(o[2*p],   ph, vl_);
                mma16816(o[2*p],   pl, vb);
                mma16816(o[2*p+1], ph, vb + 2); mma16816(o[2*p+1], ph, vl_ + 2);
                mma16816(o[2*p+1], pl, vb + 2);
            }
        }
        __syncthreads();
    }

    // single cross-thread l reduction (sum over the 4 lanes sharing each row)
    l0 += __shfl_xor_sync(0xffffffffu, l0, 1);
    l0 += __shfl_xor_sync(0xffffffffu, l0, 2);
    l1 += __shfl_xor_sync(0xffffffffu, l1, 1);
    l1 += __shfl_xor_sync(0xffffffffu, l1, 2);

    const int r = q0 + w * 16 + (lane >> 2);
    #pragma unroll
    for (int nt = 0; nt < 8; nt++) {
        const int c = nt * 8 + (lane & 3) * 2;
        *(float2*)&gP[((size_t)(n * LSEQ + r)) * D + c]     = make_float2(o[nt][0], o[nt][1]);
        *(float2*)&gP[((size_t)(n * LSEQ + r + 8)) * D + c] = make_float2(o[nt][2], o[nt][3]);
    }
    if ((lane & 3) == 0) {
        gL[n * LSEQ + r]     = l0;
        gL[n * LSEQ + r + 8] = l1;
    }
}

// ---------------------------------------------------------------------------
// Kernel 3: combine halves: out = (P0+P1)/(l0+l1)  — round-8 version.
// ---------------------------------------------------------------------------
__global__ __launch_bounds__(256) void combine_k(float* __restrict__ out)
{
    const int id = blockIdx.x * 256 + threadIdx.x;   // 512 blocks x 256 = 131072 float4s
    const int e0 = id * 4;
    const int row = e0 >> 6, c = e0 & 63;
    const float inv = 1.f / (g_l0[row] + g_l1[row]);
    const float4 a = *(const float4*)&g_p0[(size_t)row * D + c];
    const float4 b = *(const float4*)&g_p1[(size_t)row * D + c];
    float4 r;
    r.x = (a.x + b.x) * inv; r.y = (a.y + b.y) * inv;
    r.z = (a.z + b.z) * inv; r.w = (a.w + b.w) * inv;
    *(float4*)&out[(size_t)row * D + c] = r;
}

// ---------------------------------------------------------------------------
// Launch
// ---------------------------------------------------------------------------
extern "C" void kernel_launch(void* const* d_in, const int* in_sizes, int n_in,
                              void* d_out, int out_size)
{
    const float* q  = (const float*)d_in[0];
    const float* k  = (const float*)d_in[1];
    const float* v  = (const float*)d_in[2];
    const float* Wq = (const float*)d_in[3];
    const float* bq = (const float*)d_in[4];
    const float* Wk = (const float*)d_in[5];
    const float* bk = (const float*)d_in[6];
    const float* Wv = (const float*)d_in[7];
    const float* bv = (const float*)d_in[8];
    float* out = (float*)d_out;

    const int smem_proj = 4 * 64 * LDB * 2;                 // 36864 B
    const int smem_attn = 2 * 64 * LDB * 2 + 2 * STG;       // 92160 B
    cudaFuncSetAttribute(proj_mma, cudaFuncAttributeMaxDynamicSharedMemorySize, smem_proj);
    cudaFuncSetAttribute(attn_mma, cudaFuncAttributeMaxDynamicSharedMemorySize, smem_attn);

    proj_mma<<<dim3(MROWS / 64, 3), 128, smem_proj>>>(q, k, v, Wq, Wk, Wv, bq, bk, bv);
    attn_mma<<<dim3(LSEQ / 64, NB, 2), 128, smem_attn>>>();
    combine_k<<<512, 256>>>(out);
}

// round 16
// speedup vs baseline: 1.1886x; 1.0074x over previous
// Attempt 3 of the Q-overlay occupancy kernel (prior two rounds died at the
// GB300 broker before compile; R13 proved this launch config itself runs).
#include <cuda_runtime.h>
#include <cstdint>

#define H_IN  1024
#define D     64
#define NB    4
#define LSEQ  2048
#define MROWS (NB*LSEQ)     // 8192
#define LDB   72            // smem row stride (bf16 elems): 144B
#define NTL   16            // KV tiles per attn CTA (half of 32)

// Pre-split projected tensors (hi/lo bf16). Q pre-scaled by 1/(8*ln2).
__device__ uint16_t g_qh[MROWS * D];
__device__ uint16_t g_ql[MROWS * D];
__device__ uint16_t g_kh[MROWS * D];
__device__ uint16_t g_kl[MROWS * D];
__device__ uint16_t g_vh[MROWS * D];
__device__ uint16_t g_vl[MROWS * D];
// Split-KV partials (unnormalized O and denominator l)
__device__ float g_p0[MROWS * D];
__device__ float g_p1[MROWS * D];
__device__ float g_l0[MROWS];
__device__ float g_l1[MROWS];

// ---------------------------------------------------------------------------
// helpers
// ---------------------------------------------------------------------------
__device__ __forceinline__ uint32_t s2u(const void* p) {
    uint32_t a;
    asm("{.reg .u64 t; cvta.to.shared.u64 t, %1; cvt.u32.u64 %0, t;}" : "=r"(a) : "l"(p));
    return a;
}
__device__ __forceinline__ void ldsm_x4(uint32_t* r, uint32_t addr) {
    asm volatile("ldmatrix.sync.aligned.m8n8.x4.shared.b16 {%0,%1,%2,%3}, [%4];"
                 : "=r"(r[0]), "=r"(r[1]), "=r"(r[2]), "=r"(r[3]) : "r"(addr));
}
__device__ __forceinline__ void ldsm_x4_t(uint32_t* r, uint32_t addr) {
    asm volatile("ldmatrix.sync.aligned.m8n8.x4.trans.shared.b16 {%0,%1,%2,%3}, [%4];"
                 : "=r"(r[0]), "=r"(r[1]), "=r"(r[2]), "=r"(r[3]) : "r"(addr));
}
__device__ __forceinline__ void mma16816(float* c, const uint32_t* a, const uint32_t* b) {
    asm volatile("mma.sync.aligned.m16n8k16.row.col.f32.bf16.bf16.f32 "
                 "{%0,%1,%2,%3}, {%4,%5,%6,%7}, {%8,%9}, {%0,%1,%2,%3};"
                 : "+f"(c[0]), "+f"(c[1]), "+f"(c[2]), "+f"(c[3])
                 : "r"(a[0]), "r"(a[1]), "r"(a[2]), "r"(a[3]), "r"(b[0]), "r"(b[1]));
}
__device__ __forceinline__ void split4(float4 v, uint2& hi, uint2& lo) {
    uint32_t ux = __float_as_uint(v.x), uy = __float_as_uint(v.y);
    uint32_t uz = __float_as_uint(v.z), uw = __float_as_uint(v.w);
    asm("prmt.b32 %0, %1, %2, 0x7632;" : "=r"(hi.x) : "r"(ux), "r"(uy));
    asm("prmt.b32 %0, %1, %2, 0x7632;" : "=r"(hi.y) : "r"(uz), "r"(uw));
    float rx = v.x - __uint_as_float(ux & 0xFFFF0000u);
    float ry = v.y - __uint_as_float(uy & 0xFFFF0000u);
    float rz = v.z - __uint_as_float(uz & 0xFFFF0000u);
    float rw = v.w - __uint_as_float(uw & 0xFFFF0000u);
    asm("cvt.rn.bf16x2.f32 %0, %1, %2;" : "=r"(lo.x) : "f"(ry), "f"(rx));
    asm("cvt.rn.bf16x2.f32 %0, %1, %2;" : "=r"(lo.y) : "f"(rw), "f"(rz));
}
__device__ __forceinline__ uint32_t pack_hi(float a, float b) {
    uint32_t r;
    asm("prmt.b32 %0, %1, %2, 0x7632;" : "=r"(r)
        : "r"(__float_as_uint(a)), "r"(__float_as_uint(b)));
    return r;
}
__device__ __forceinline__ uint32_t pack_lo(float a, float b) {
    float ra = a - __uint_as_float(__float_as_uint(a) & 0xFFFF0000u);
    float rb = b - __uint_as_float(__float_as_uint(b) & 0xFFFF0000u);
    uint32_t r;
    asm("cvt.rn.bf16x2.f32 %0, %1, %2;" : "=r"(r) : "f"(rb), "f"(ra));
    return r;
}
__device__ __forceinline__ float ex2(float x) {
    float y;
    asm("ex2.approx.f32 %0, %1;" : "=f"(y) : "f"(x));
    return y;
}
template <int N> __device__ __forceinline__ void cp_wait() {
    asm volatile("cp.async.wait_group %0;" :: "n"(N) : "memory");
}
__device__ __forceinline__ void cp_commit() {
    asm volatile("cp.async.commit_group;" ::: "memory");
}
__device__ __forceinline__ void cp16(uint32_t saddr, const void* gaddr) {
    asm volatile("cp.async.cg.shared.global [%0], [%1], 16;"
                 :: "r"(saddr), "l"(gaddr) : "memory");
}

// ---------------------------------------------------------------------------
// Kernel 1: QKV projection — EXACT round-8/11 version (measured 45.2us).
// 128 threads (4 warps), CTA tile M=64, K-chunk 64; grid (128, 3).
// ---------------------------------------------------------------------------
__global__ __launch_bounds__(128) void proj_mma(
    const float* __restrict__ Xq, const float* __restrict__ Xk, const float* __restrict__ Xv,
    const float* __restrict__ Wq, const float* __restrict__ Wk, const float* __restrict__ Wv,
    const float* __restrict__ Bq, const float* __restrict__ Bk, const float* __restrict__ Bv)
{
    const float* X; const float* W; const float* Bias;
    uint16_t* outH; uint16_t* outL; float scale;
    switch (blockIdx.y) {
        case 0:  X = Xq; W = Wq; Bias = Bq; outH = g_qh; outL = g_ql;
                 scale = 0.18033688f; break;             // 1/(8*ln2)
        case 1:  X = Xk; W = Wk; Bias = Bk; outH = g_kh; outL = g_kl; scale = 1.0f; break;
        default: X = Xv; W = Wv; Bias = Bv; outH = g_vh; outL = g_vl; scale = 1.0f; break;
    }

    extern __shared__ uint16_t sp[];
    uint16_t* Ah = sp;
    uint16_t* Al = Ah + 64 * LDB;
    uint16_t* Bh = Al + 64 * LDB;
    uint16_t* Bl = Bh + 64 * LDB;

    const int tid  = threadIdx.x;
    const int lane = tid & 31;
    const int w    = tid >> 5;
    const int m0   = blockIdx.x * 64;
    const int g    = lane >> 3, l8 = lane & 7;

    float acc[8][4];
    #pragma unroll
    for (int nt = 0; nt < 8; nt++)
        #pragma unroll
        for (int j = 0; j < 4; j++) acc[nt][j] = 0.f;

    float4 xv[8];
    #pragma unroll
    for (int i = 0; i < 8; i++) {
        const int idx = tid + i * 128;
        xv[i] = *(const float4*)&X[(size_t)(m0 + (idx >> 4)) * H_IN + (idx & 15) * 4];
    }

    for (int kk = 0; kk < H_IN; kk += 64) {
        float4 wv[8];
        #pragma unroll
        for (int i = 0; i < 8; i++) {
            const int idx = tid + i * 128;
            wv[i] = *(const float4*)&W[(size_t)(kk + (idx >> 4)) * D + (idx & 15) * 4];
        }
        #pragma unroll
        for (int i = 0; i < 8; i++) {
            const int idx = tid + i * 128;
            const int row = idx >> 4, f4 = idx & 15;
            uint2 hi, lo; split4(xv[i], hi, lo);
            *(uint2*)&Ah[row * LDB + f4 * 4] = hi;
            *(uint2*)&Al[row * LDB + f4 * 4] = lo;
        }
        #pragma unroll
        for (int i = 0; i < 8; i++) {
            const int idx = tid + i * 128;
            const int row = idx >> 4, f4 = idx & 15;
            uint2 hi, lo; split4(wv[i], hi, lo);
            *(uint2*)&Bh[row * LDB + f4 * 4] = hi;
            *(uint2*)&Bl[row * LDB + f4 * 4] = lo;
        }
        __syncthreads();

        if (kk + 64 < H_IN) {
            #pragma unroll
            for (int i = 0; i < 8; i++) {
                const int idx = tid + i * 128;
                xv[i] = *(const float4*)&X[(size_t)(m0 + (idx >> 4)) * H_IN + kk + 64 + (idx & 15) * 4];
            }
        }

        uint32_t ah[4], al[4], bb[4], bl[4];
        #pragma unroll
        for (int kt = 0; kt < 4; kt++) {
            const int aoff = (w * 16 + (lane & 15)) * LDB + kt * 16 + (lane >> 4) * 8;
            ldsm_x4(ah, s2u(&Ah[aoff]));
            ldsm_x4(al, s2u(&Al[aoff]));
            #pragma unroll
            for (int p = 0; p < 4; p++) {
                const int row = kt * 16 + (g & 1) * 8 + l8;
                const int col = (2 * p + (g >> 1)) * 8;
                ldsm_x4_t(bb, s2u(&Bh[row * LDB + col]));
                ldsm_x4_t(bl, s2u(&Bl[row * LDB + col]));
                mma16816(acc[2*p],   ah, bb);     mma16816(acc[2*p],   ah, bl);
                mma16816(acc[2*p],   al, bb);
                mma16816(acc[2*p+1], ah, bb + 2); mma16816(acc[2*p+1], ah, bl + 2);
                mma16816(acc[2*p+1], al, bb + 2);
            }
        }
        __syncthreads();
    }

    const int r0 = m0 + w * 16 + (lane >> 2);
    #pragma unroll
    for (int nt = 0; nt < 8; nt++) {
        const int c = nt * 8 + (lane & 3) * 2;
        const float2 b2 = *(const float2*)&Bias[c];
        const float y0 = (acc[nt][0] + b2.x) * scale;
        const float y1 = (acc[nt][1] + b2.y) * scale;
        const float y2 = (acc[nt][2] + b2.x) * scale;
        const float y3 = (acc[nt][3] + b2.y) * scale;
        *(uint32_t*)&outH[(size_t)r0 * D + c]       = pack_hi(y0, y1);
        *(uint32_t*)&outL[(size_t)r0 * D + c]       = pack_lo(y0, y1);
        *(uint32_t*)&outH[(size_t)(r0 + 8) * D + c] = pack_hi(y2, y3);
        *(uint32_t*)&outL[(size_t)(r0 + 8) * D + c] = pack_lo(y2, y3);
    }
}

// ---------------------------------------------------------------------------
// Kernel 2: flash attention. SMEM = 2 KV stages ONLY (73.7KB -> 3 CTAs/SM).
// Q overlays stage 0 (dead after fragment preload). Tile j -> stage (j+1)&1.
// R11 ISSUE SCHEDULE: exactly one prefetch in flight — at iteration t, issue
// tile t+1 into stage t&1 (whose reads were closed by the previous barrier;
// at t=0 that is the Q overlay, closed by the post-fragment barrier).
// split-KV(2), no-max base-2 softmax, warp-independent rows.
// ---------------------------------------------------------------------------
#define STG 36864
#define ARR 9216

__device__ __forceinline__ void issue_kv(uint32_t kvb, int n, int tile, int tid) {
    #pragma unroll
    for (int j = 0; j < 16; j++) {
        const int cc = tid + j * 128;
        const int arr = cc >> 9, rem = cc & 511, row = rem >> 3, col = rem & 7;
        const uint16_t* gp = (arr == 0) ? g_kh : (arr == 1) ? g_kl
                            : (arr == 2) ? g_vh : g_vl;
        cp16(kvb + arr * ARR + row * 144 + col * 16,
             gp + ((size_t)(n * LSEQ + tile * 64 + row)) * D + col * 8);
    }
    cp_commit();
}

__global__ __launch_bounds__(128) void attn_mma(void)
{
    extern __shared__ uint16_t sa[];
    uint16_t* Qh = sa;                  // overlays KV stage 0 (dead after preload)
    uint16_t* Ql = Qh + 64 * LDB;
    const uint32_t kvb = s2u(sa);

    const int tid  = threadIdx.x;
    const int lane = tid & 31;
    const int w    = tid >> 5;
    const int g    = lane >> 3, l8 = lane & 7;
    const int n    = blockIdx.y;
    const int q0   = blockIdx.x * 64;
    const int z    = blockIdx.z;
    const int off  = (blockIdx.x * 7 + blockIdx.y * 5 + z * 3) & (NTL - 1);
    #define TL(t) (z * NTL + (((t) + off) & (NTL - 1)))

    float* gP = z ? g_p1 : g_p0;
    float* gL = z ? g_l1 : g_l0;

    // prologue: ONLY tile0 -> stage1 (disjoint from Q overlay region)
    issue_kv(kvb + 1 * STG, n, TL(0), tid);
    #pragma unroll
    for (int j = 0; j < 8; j++) {
        const int cc = tid + j * 128;
        const int a = cc >> 9, rem = cc & 511, row = rem >> 3, col = rem & 7;
        uint16_t* spq = a ? Ql : Qh;
        *(uint4*)&spq[row * LDB + col * 8] =
            *(const uint4*)&(a ? g_ql : g_qh)[((size_t)(n * LSEQ + q0 + row)) * D + col * 8];
    }
    __syncthreads();

    uint32_t qh[4][4], ql[4][4];
    #pragma unroll
    for (int kt = 0; kt < 4; kt++) {
        const int aoff = (w * 16 + (lane & 15)) * LDB + kt * 16 + (lane >> 4) * 8;
        ldsm_x4(qh[kt], s2u(&Qh[aoff]));
        ldsm_x4(ql[kt], s2u(&Ql[aoff]));
    }
    __syncthreads();                     // closes ALL Q reads before stage0 reuse

    float o[8][4];
    #pragma unroll
    for (int nt = 0; nt < 8; nt++)
        #pragma unroll
        for (int j = 0; j < 4; j++) o[nt][j] = 0.f;
    float l0 = 0.f, l1 = 0.f;            // per-thread partials; reduced at end

    for (int t = 0; t < NTL; t++) {
        const uint32_t st = kvb + ((t + 1) & 1) * STG;   // tile t lives in stage (t+1)&1
        if (t + 1 < NTL) {
            issue_kv(kvb + (t & 1) * STG, n, TL(t + 1), tid);  // tile t+1 -> stage t&1
            cp_wait<1>();                                      // tile t complete
        } else {
            cp_wait<0>();
        }
        __syncthreads();

        float s[8][4];
        #pragma unroll
        for (int nt = 0; nt < 8; nt++)
            #pragma unroll
            for (int j = 0; j < 4; j++) s[nt][j] = 0.f;

        #pragma unroll
        for (int kt = 0; kt < 4; kt++) {
            #pragma unroll
            for (int p = 0; p < 4; p++) {
                const int row  = p * 16 + (g >> 1) * 8 + l8;
                const int koff = kt * 16 + (g & 1) * 8;
                uint32_t kb[4], kl_[4];
                ldsm_x4(kb,  st + 0 * ARR + (row * LDB + koff) * 2);
                ldsm_x4(kl_, st + 1 * ARR + (row * LDB + koff) * 2);
                mma16816(s[2*p],   qh[kt], kb);     mma16816(s[2*p],   qh[kt], kl_);
                mma16816(s[2*p],   ql[kt], kb);
                mma16816(s[2*p+1], qh[kt], kb + 2); mma16816(s[2*p+1], qh[kt], kl_ + 2);
                mma16816(s[2*p+1], ql[kt], kb + 2);
            }
        }

        // no-max base-2 softmax; l kept per-thread (no shuffles in loop)
        #pragma unroll
        for (int nt = 0; nt < 8; nt++) {
            s[nt][0] = ex2(s[nt][0]); l0 += s[nt][0];
            s[nt][1] = ex2(s[nt][1]); l0 += s[nt][1];
            s[nt][2] = ex2(s[nt][2]); l1 += s[nt][2];
            s[nt][3] = ex2(s[nt][3]); l1 += s[nt][3];
        }

        #pragma unroll
        for (int kt = 0; kt < 4; kt++) {
            uint32_t ph[4], pl[4];
            ph[0] = pack_hi(s[2*kt][0],   s[2*kt][1]);
            ph[1] = pack_hi(s[2*kt][2],   s[2*kt][3]);
            ph[2] = pack_hi(s[2*kt+1][0], s[2*kt+1][1]);
            ph[3] = pack_hi(s[2*kt+1][2], s[2*kt+1][3]);
            pl[0] = pack_lo(s[2*kt][0],   s[2*kt][1]);
            pl[1] = pack_lo(s[2*kt][2],   s[2*kt][3]);
            pl[2] = pack_lo(s[2*kt+1][0], s[2*kt+1][1]);
            pl[3] = pack_lo(s[2*kt+1][2], s[2*kt+1][3]);
            #pragma unroll
            for (int p = 0; p < 4; p++) {
                const int row = kt * 16 + (g & 1) * 8 + l8;
                const int col = (2 * p + (g >> 1)) * 8;
                uint32_t vb[4], vl_[4];
                ldsm_x4_t(vb,  st + 2 * ARR + (row * LDB + col) * 2);
                ldsm_x4_t(vl_, st + 3 * ARR + (row * LDB + col) * 2);
                mma16816(o[2*p],   ph, vb);     mma16816(o[2*p],   ph, vl_);
                mma16816(o[2*p],   pl, vb);
                mma16816(o[2*p+1], ph, vb + 2); mma16816(o[2*p+1], ph, vl_ + 2);
                mma16816(o[2*p+1], pl, vb + 2);
            }
        }
        __syncthreads();                 // closes stage reads before its reuse
    }

    // single cross-thread l reduction
    l0 += __shfl_xor_sync(0xffffffffu, l0, 1);
    l0 += __shfl_xor_sync(0xffffffffu, l0, 2);
    l1 += __shfl_xor_sync(0xffffffffu, l1, 1);
    l1 += __shfl_xor_sync(0xffffffffu, l1, 2);

    const int r = q0 + w * 16 + (lane >> 2);
    #pragma unroll
    for (int nt = 0; nt < 8; nt++) {
        const int c = nt * 8 + (lane & 3) * 2;
        *(float2*)&gP[((size_t)(n * LSEQ + r)) * D + c]     = make_float2(o[nt][0], o[nt][1]);
        *(float2*)&gP[((size_t)(n * LSEQ + r + 8)) * D + c] = make_float2(o[nt][2], o[nt][3]);
    }
    if ((lane & 3) == 0) {
        gL[n * LSEQ + r]     = l0;
        gL[n * LSEQ + r + 8] = l1;
    }
}

// ---------------------------------------------------------------------------
// Kernel 3: combine halves: out = (P0+P1)/(l0+l1)  — round-8/11 version.
// ---------------------------------------------------------------------------
__global__ __launch_bounds__(256) void combine_k(float* __restrict__ out)
{
    const int id = blockIdx.x * 256 + threadIdx.x;
    const int e0 = id * 4;
    const int row = e0 >> 6, c = e0 & 63;
    const float inv = 1.f / (g_l0[row] + g_l1[row]);
    const float4 a = *(const float4*)&g_p0[(size_t)row * D + c];
    const float4 b = *(const float4*)&g_p1[(size_t)row * D + c];
    float4 r;
    r.x = (a.x + b.x) * inv; r.y = (a.y + b.y) * inv;
    r.z = (a.z + b.z) * inv; r.w = (a.w + b.w) * inv;
    *(float4*)&out[(size_t)row * D + c] = r;
}

// ---------------------------------------------------------------------------
// Launch
// ---------------------------------------------------------------------------
extern "C" void kernel_launch(void* const* d_in, const int* in_sizes, int n_in,
                              void* d_out, int out_size)
{
    const float* q  = (const float*)d_in[0];
    const float* k  = (const float*)d_in[1];
    const float* v  = (const float*)d_in[2];
    const float* Wq = (const float*)d_in[3];
    const float* bq = (const float*)d_in[4];
    const float* Wk = (const float*)d_in[5];
    const float* bk = (const float*)d_in[6];
    const float* Wv = (const float*)d_in[7];
    const float* bv = (const float*)d_in[8];
    float* out = (float*)d_out;

    const int smem_proj = 4 * 64 * LDB * 2;   // 36864 B
    const int smem_attn = 2 * STG;            // 73728 B -> 3 CTAs/SM
    cudaFuncSetAttribute(proj_mma, cudaFuncAttributeMaxDynamicSharedMemorySize, smem_proj);
    cudaFuncSetAttribute(attn_mma, cudaFuncAttributeMaxDynamicSharedMemorySize, smem_attn);

    proj_mma<<<dim3(MROWS / 64, 3), 128, smem_proj>>>(q, k, v, Wq, Wk, Wv, bq, bk, bv);
    attn_mma<<<dim3(LSEQ / 64, NB, 2), 128, smem_attn>>>();
    combine_k<<<512, 256>>>(out);
}